// round 1
// baseline (speedup 1.0000x reference)
#include <cuda_runtime.h>
#include <cuda_bf16.h>

#define NROWS 4096
#define DIM 256
#define INV_T 10.0f
#define EXPSC 14.4269504088896340736f  /* 10 * log2(e) */

// persistent device scratch (no allocations allowed)
__device__ __nv_bfloat16 g_z1[NROWS * DIM];
__device__ __nv_bfloat16 g_z2[NROWS * DIM];
__device__ float g_rowsum[4][NROWS];   // 0: rs12, 1: rs21(=colsum12), 2: rs11 masked, 3: rs22 masked
__device__ float g_diag[NROWS];        // sim12[i,i] * 10

__device__ __forceinline__ float fast_ex2(float x) {
    float y;
    asm("ex2.approx.f32 %0, %1;" : "=f"(y) : "f"(x));
    return y;
}

// ---------------------------------------------------------------------------
// Kernel 1: L2-normalize rows (eps clamp like torch CosineSimilarity), fp32->bf16
// one warp per row
// ---------------------------------------------------------------------------
__global__ void normalize_kernel(const float* __restrict__ x1,
                                 const float* __restrict__ x2) {
    int gw = (blockIdx.x * blockDim.x + threadIdx.x) >> 5;
    int lane = threadIdx.x & 31;
    const float* src;
    __nv_bfloat16* dst;
    int row;
    if (gw < NROWS) { src = x1; dst = g_z1; row = gw; }
    else            { src = x2; dst = g_z2; row = gw - NROWS; }

    const float4* p = (const float4*)(src + row * DIM);
    float4 a = p[lane];
    float4 b = p[lane + 32];
    float s = a.x*a.x + a.y*a.y + a.z*a.z + a.w*a.w
            + b.x*b.x + b.y*b.y + b.z*b.z + b.w*b.w;
#pragma unroll
    for (int o = 16; o; o >>= 1) s += __shfl_xor_sync(0xffffffffu, s, o);
    float sc = 1.0f / fmaxf(sqrtf(s), 1e-8f);

    __nv_bfloat162 h0 = __floats2bfloat162_rn(a.x * sc, a.y * sc);
    __nv_bfloat162 h1 = __floats2bfloat162_rn(a.z * sc, a.w * sc);
    __nv_bfloat162 h2 = __floats2bfloat162_rn(b.x * sc, b.y * sc);
    __nv_bfloat162 h3 = __floats2bfloat162_rn(b.z * sc, b.w * sc);
    uint2 u0 = make_uint2(*(unsigned*)&h0, *(unsigned*)&h1);
    uint2 u1 = make_uint2(*(unsigned*)&h2, *(unsigned*)&h3);
    *(uint2*)(dst + row * DIM + lane * 4) = u0;
    *(uint2*)(dst + row * DIM + 128 + lane * 4) = u1;
}

// ---------------------------------------------------------------------------
// Kernel 2: fused tile-GEMM + exp row-reduce.
// grid = 128 CTAs: pass = bid & 3, itile = bid >> 2 (32 row tiles of 128).
// Each CTA: loads its 128x256 bf16 A stripe once, streams 32 column tiles of B
// (double-buffered cp.async), mma.sync bf16 -> fp32, exp2 epilogue, register
// row partials, final smem reduce, writes g_rowsum[pass][...].
// ---------------------------------------------------------------------------
#define SWZ(r, c) (((r) << 9) | ((((c) ^ ((r) & 7))) << 4))

__device__ __forceinline__ void cp16(unsigned d, const void* s) {
    asm volatile("cp.async.cg.shared.global [%0], [%1], 16;" :: "r"(d), "l"(s));
}
__device__ __forceinline__ void cp_commit() {
    asm volatile("cp.async.commit_group;");
}
template <int n>
__device__ __forceinline__ void cp_wait() {
    asm volatile("cp.async.wait_group %0;" :: "n"(n));
}
__device__ __forceinline__ void ldsm4(unsigned (&r)[4], unsigned addr) {
    asm volatile("ldmatrix.sync.aligned.m8n8.x4.shared.b16 {%0,%1,%2,%3}, [%4];"
                 : "=r"(r[0]), "=r"(r[1]), "=r"(r[2]), "=r"(r[3]) : "r"(addr));
}
__device__ __forceinline__ void mma16816(float (&d)[4], const unsigned (&a)[4],
                                         unsigned b0, unsigned b1) {
    asm volatile(
        "mma.sync.aligned.m16n8k16.row.col.f32.bf16.bf16.f32 "
        "{%0,%1,%2,%3}, {%4,%5,%6,%7}, {%8,%9}, {%0,%1,%2,%3};"
        : "+f"(d[0]), "+f"(d[1]), "+f"(d[2]), "+f"(d[3])
        : "r"(a[0]), "r"(a[1]), "r"(a[2]), "r"(a[3]), "r"(b0), "r"(b1));
}

__global__ void __launch_bounds__(256, 1) simreduce_kernel() {
    extern __shared__ __align__(128) char smem[];
    char* smA = smem;                       // 64 KB A stripe
    unsigned sA = (unsigned)__cvta_generic_to_shared(smA);
    unsigned sB[2] = {(unsigned)__cvta_generic_to_shared(smem + 65536),
                      (unsigned)__cvta_generic_to_shared(smem + 131072)};

    const int pass  = blockIdx.x & 3;
    const int itile = blockIdx.x >> 2;
    const __nv_bfloat16* A = (pass == 1 || pass == 3) ? g_z2 : g_z1;
    const __nv_bfloat16* B = (pass == 0 || pass == 3) ? g_z2 : g_z1;
    const int row0 = itile * 128;
    const int tid = threadIdx.x;

    // stage A stripe (group 0) and B tile 0 (group 1)
#pragma unroll
    for (int it = 0; it < 16; it++) {
        int idx = tid + it * 256;
        int r = idx >> 5, c = idx & 31;
        cp16(sA + SWZ(r, c), A + (row0 + r) * DIM + c * 8);
    }
    cp_commit();
#pragma unroll
    for (int it = 0; it < 16; it++) {
        int idx = tid + it * 256;
        int r = idx >> 5, c = idx & 31;
        cp16(sB[0] + SWZ(r, c), B + r * DIM + c * 8);
    }
    cp_commit();

    const int lane  = tid & 31;
    const int warpid = tid >> 5;
    const int warpM = warpid & 3;    // 4 warps over 128 M rows (32 each)
    const int warpN = warpid >> 1 & 0; // placeholder (see below)
    const int wN    = warpid >> 2;   // 2 warps over 128 N cols (64 each)
    (void)warpN;
    const int lrow = lane & 7, quad = lane >> 3;

    // ldmatrix address components
    int aRow[2];
#pragma unroll
    for (int mi = 0; mi < 2; mi++) aRow[mi] = warpM * 32 + mi * 16 + lrow + (quad & 1) * 8;
    const int aCq = quad >> 1;
    int bRow[4];
#pragma unroll
    for (int p = 0; p < 4; p++) bRow[p] = wN * 64 + p * 16 + lrow + (quad >> 1) * 8;
    const int bCq = quad & 1;

    const int erow = lane >> 2;          // epilogue: accumulator row within frag
    const int ecol = (lane & 3) * 2;     // epilogue: accumulator col within n8

    float part[4] = {0.f, 0.f, 0.f, 0.f};
    const bool needMask = (pass >= 2);

    for (int j = 0; j < 32; j++) {
        if (j + 1 < 32) {
            unsigned dB = sB[(j + 1) & 1];
#pragma unroll
            for (int it = 0; it < 16; it++) {
                int idx = tid + it * 256;
                int r = idx >> 5, c = idx & 31;
                cp16(dB + SWZ(r, c), B + ((j + 1) * 128 + r) * DIM + c * 8);
            }
            cp_commit();
            cp_wait<1>();
        } else {
            cp_wait<0>();
        }
        __syncthreads();

        unsigned sBj = sB[j & 1];
        float acc[2][8][4];
#pragma unroll
        for (int mi = 0; mi < 2; mi++)
#pragma unroll
            for (int ni = 0; ni < 8; ni++)
#pragma unroll
                for (int k = 0; k < 4; k++) acc[mi][ni][k] = 0.f;

#pragma unroll
        for (int ks = 0; ks < 16; ks++) {
            unsigned a[2][4];
#pragma unroll
            for (int mi = 0; mi < 2; mi++) {
                unsigned addr = sA + (aRow[mi] << 9) +
                                (((2 * ks + aCq) ^ (aRow[mi] & 7)) << 4);
                ldsm4(a[mi], addr);
            }
            unsigned b[4][4];
#pragma unroll
            for (int p = 0; p < 4; p++) {
                unsigned addr = sBj + (bRow[p] << 9) +
                                (((2 * ks + bCq) ^ (bRow[p] & 7)) << 4);
                ldsm4(b[p], addr);
            }
#pragma unroll
            for (int mi = 0; mi < 2; mi++)
#pragma unroll
                for (int ni = 0; ni < 8; ni++)
                    mma16816(acc[mi][ni], a[mi],
                             b[ni >> 1][(ni & 1) * 2], b[ni >> 1][(ni & 1) * 2 + 1]);
        }

        // epilogue: exp(10 * sim) via ex2, diag mask / diag record, row partials
        const bool dj = (j == itile) && (needMask || pass == 0);
#pragma unroll
        for (int mi = 0; mi < 2; mi++) {
            float s0 = 0.f, s1 = 0.f;
            int rr0 = warpM * 32 + mi * 16 + erow;
            int rr1 = rr0 + 8;
#pragma unroll
            for (int ni = 0; ni < 8; ni++) {
                float c0 = acc[mi][ni][0], c1 = acc[mi][ni][1];
                float c2 = acc[mi][ni][2], c3 = acc[mi][ni][3];
                float e0 = fast_ex2(c0 * EXPSC), e1 = fast_ex2(c1 * EXPSC);
                float e2 = fast_ex2(c2 * EXPSC), e3 = fast_ex2(c3 * EXPSC);
                if (dj) {
                    int cc0 = wN * 64 + ni * 8 + ecol;
                    int cc1 = cc0 + 1;
                    if (needMask) {
                        if (rr0 == cc0) e0 = 0.f;
                        if (rr0 == cc1) e1 = 0.f;
                        if (rr1 == cc0) e2 = 0.f;
                        if (rr1 == cc1) e3 = 0.f;
                    } else {  // pass == 0: record sim12 diagonal
                        if (rr0 == cc0) g_diag[row0 + rr0] = c0 * INV_T;
                        if (rr0 == cc1) g_diag[row0 + rr0] = c1 * INV_T;
                        if (rr1 == cc0) g_diag[row0 + rr1] = c2 * INV_T;
                        if (rr1 == cc1) g_diag[row0 + rr1] = c3 * INV_T;
                    }
                }
                s0 += e0 + e1;
                s1 += e2 + e3;
            }
            part[mi * 2 + 0] += s0;
            part[mi * 2 + 1] += s1;
        }
        __syncthreads();
    }

    // reduce the 4 lanes sharing a row, then combine the 2 N-warps via smem
#pragma unroll
    for (int k = 0; k < 4; k++) {
        part[k] += __shfl_xor_sync(0xffffffffu, part[k], 1);
        part[k] += __shfl_xor_sync(0xffffffffu, part[k], 2);
    }
    __syncthreads();
    float* rowAcc = (float*)smem;
    if (wN == 0 && (lane & 3) == 0) {
        int r = warpM * 32 + erow;
        rowAcc[r]      = part[0];
        rowAcc[r + 8]  = part[1];
        rowAcc[r + 16] = part[2];
        rowAcc[r + 24] = part[3];
    }
    __syncthreads();
    if (wN == 1 && (lane & 3) == 0) {
        int r = warpM * 32 + erow;
        atomicAdd(&rowAcc[r],      part[0]);
        atomicAdd(&rowAcc[r + 8],  part[1]);
        atomicAdd(&rowAcc[r + 16], part[2]);
        atomicAdd(&rowAcc[r + 24], part[3]);
    }
    __syncthreads();
    if (tid < 128) g_rowsum[pass][row0 + tid] = rowAcc[tid];
}

// ---------------------------------------------------------------------------
// Kernel 3: final losses.
// row i    : lse(sim12 row + masked sim11 row) - sim12[i,i]/T
// row N+i  : lse(masked sim22 row + sim12 col) - sim12[i,i]/T
// ---------------------------------------------------------------------------
__global__ void loss_kernel(float* __restrict__ out) {
    int i = blockIdx.x * blockDim.x + threadIdx.x;
    if (i < NROWS) {
        float d = g_diag[i];
        out[i]         = logf(g_rowsum[0][i] + g_rowsum[2][i]) - d;
        out[NROWS + i] = logf(g_rowsum[3][i] + g_rowsum[1][i]) - d;
    }
}

extern "C" void kernel_launch(void* const* d_in, const int* in_sizes, int n_in,
                              void* d_out, int out_size) {
    const float* x1 = (const float*)d_in[0];
    const float* x2 = (const float*)d_in[1];

    normalize_kernel<<<1024, 256>>>(x1, x2);

    cudaFuncSetAttribute(simreduce_kernel,
                         cudaFuncAttributeMaxDynamicSharedMemorySize, 196608);
    simreduce_kernel<<<128, 256, 196608>>>();

    loss_kernel<<<16, 256>>>((float*)d_out);
}

// round 2
// speedup vs baseline: 1.4446x; 1.4446x over previous
#include <cuda_runtime.h>
#include <cuda_bf16.h>

#define NROWS 4096
#define DIM 256
#define INV_T 10.0f
#define EXPSC 14.4269504088896340736f  /* 10 * log2(e) */

// persistent device scratch (no allocations allowed)
__device__ __nv_bfloat16 g_z1[NROWS * DIM];
__device__ __nv_bfloat16 g_z2[NROWS * DIM];
// 0: rowsum(exp sim12), 1: colsum(exp sim12), 2: rowsum(exp sim11 masked), 3: rowsum(exp sim22 masked)
__device__ float g_rowsum[4][NROWS];
__device__ float g_diag[NROWS];        // sim12[i,i] * 10

__device__ __forceinline__ float fast_ex2(float x) {
    float y;
    asm("ex2.approx.f32 %0, %1;" : "=f"(y) : "f"(x));
    return y;
}

// ---------------------------------------------------------------------------
// Kernel 1: L2-normalize rows (eps clamp), fp32->bf16. One warp per row.
// Also zero-initializes g_rowsum.
// ---------------------------------------------------------------------------
__global__ void normalize_kernel(const float* __restrict__ x1,
                                 const float* __restrict__ x2) {
    int gt = blockIdx.x * blockDim.x + threadIdx.x;
    if (gt < 4 * NROWS) (&g_rowsum[0][0])[gt] = 0.0f;

    int gw = gt >> 5;
    int lane = threadIdx.x & 31;
    const float* src;
    __nv_bfloat16* dst;
    int row;
    if (gw < NROWS) { src = x1; dst = g_z1; row = gw; }
    else            { src = x2; dst = g_z2; row = gw - NROWS; }

    const float4* p = (const float4*)(src + row * DIM);
    float4 a = p[lane];
    float4 b = p[lane + 32];
    float s = a.x*a.x + a.y*a.y + a.z*a.z + a.w*a.w
            + b.x*b.x + b.y*b.y + b.z*b.z + b.w*b.w;
#pragma unroll
    for (int o = 16; o; o >>= 1) s += __shfl_xor_sync(0xffffffffu, s, o);
    float sc = 1.0f / fmaxf(sqrtf(s), 1e-8f);

    __nv_bfloat162 h0 = __floats2bfloat162_rn(a.x * sc, a.y * sc);
    __nv_bfloat162 h1 = __floats2bfloat162_rn(a.z * sc, a.w * sc);
    __nv_bfloat162 h2 = __floats2bfloat162_rn(b.x * sc, b.y * sc);
    __nv_bfloat162 h3 = __floats2bfloat162_rn(b.z * sc, b.w * sc);
    uint2 u0 = make_uint2(*(unsigned*)&h0, *(unsigned*)&h1);
    uint2 u1 = make_uint2(*(unsigned*)&h2, *(unsigned*)&h3);
    *(uint2*)(dst + row * DIM + lane * 4) = u0;
    *(uint2*)(dst + row * DIM + 128 + lane * 4) = u1;
}

// ---------------------------------------------------------------------------
// Kernel 2: fused tile-GEMM + exp row/col-reduce, symmetry-aware.
// 128 CTAs:
//   bid <  64 : sim12. stripe i = bid>>1, j-half h = bid&1 (16 tiles).
//               rowsums -> g_rowsum[0], colsums -> g_rowsum[1], diag recorded.
//   bid >= 64 : symmetric sim11 (m=0) / sim22 (m=1). 32 CTAs per matrix.
//               pair p = stripes (p, 31-p): 33 upper-tri tiles split 17/16.
//               diag tiles masked; off-diag tiles contribute rowsums (stripe)
//               AND colsums (by symmetry -> rows of stripe j).
// ---------------------------------------------------------------------------
#define SWZ(r, c) (((r) << 9) | ((((c) ^ ((r) & 7))) << 4))
#define SMEM_A 0
#define SMEM_B0 65536
#define SMEM_B1 131072
#define SMEM_COLBUF 196608
#define SMEM_TOTAL (196608 + 2048)

__device__ __forceinline__ void cp16(unsigned d, const void* s) {
    asm volatile("cp.async.cg.shared.global [%0], [%1], 16;" :: "r"(d), "l"(s));
}
__device__ __forceinline__ void cp_commit() {
    asm volatile("cp.async.commit_group;");
}
template <int n>
__device__ __forceinline__ void cp_wait() {
    asm volatile("cp.async.wait_group %0;" :: "n"(n));
}
__device__ __forceinline__ void ldsm4(unsigned (&r)[4], unsigned addr) {
    asm volatile("ldmatrix.sync.aligned.m8n8.x4.shared.b16 {%0,%1,%2,%3}, [%4];"
                 : "=r"(r[0]), "=r"(r[1]), "=r"(r[2]), "=r"(r[3]) : "r"(addr));
}
__device__ __forceinline__ void mma16816(float (&d)[4], const unsigned (&a)[4],
                                         unsigned b0, unsigned b1) {
    asm volatile(
        "mma.sync.aligned.m16n8k16.row.col.f32.bf16.bf16.f32 "
        "{%0,%1,%2,%3}, {%4,%5,%6,%7}, {%8,%9}, {%0,%1,%2,%3};"
        : "+f"(d[0]), "+f"(d[1]), "+f"(d[2]), "+f"(d[3])
        : "r"(a[0]), "r"(a[1]), "r"(a[2]), "r"(a[3]), "r"(b0), "r"(b1));
}

__global__ void __launch_bounds__(256, 1) simreduce_kernel() {
    extern __shared__ __align__(128) char smem[];
    unsigned sA = (unsigned)__cvta_generic_to_shared(smem + SMEM_A);
    unsigned sB[2] = {(unsigned)__cvta_generic_to_shared(smem + SMEM_B0),
                      (unsigned)__cvta_generic_to_shared(smem + SMEM_B1)};
    float* colbuf = (float*)(smem + SMEM_COLBUF);  // [4][128]

    const int tid = threadIdx.x;
    const int bid = blockIdx.x;

    // ---- decode work assignment ----
    const __nv_bfloat16 *Aptr, *Bptr;
    int segStripe[2], segJ0[2], segJ1[2];
    int nseg;
    int rowTarget, colTarget;
    bool symmetric;
    if (bid < 64) {
        int i = bid >> 1, h = bid & 1;
        Aptr = g_z1; Bptr = g_z2;
        nseg = 1; segStripe[0] = i; segJ0[0] = 16 * h; segJ1[0] = 16 * h + 16;
        rowTarget = 0; colTarget = 1; symmetric = false;
    } else {
        int q = bid - 64;
        int m = q >> 5; q &= 31;
        int p = q >> 1, h = q & 1;
        Aptr = Bptr = m ? g_z2 : g_z1;
        rowTarget = colTarget = 2 + m; symmetric = true;
        int t0 = 17 * h, t1 = min(17 * h + 17, 33);
        int boundary = 32 - p;       // tiles [0, boundary) belong to stripe p
        nseg = 0;
        if (t0 < boundary) {
            int e = min(t1, boundary);
            segStripe[nseg] = p; segJ0[nseg] = p + t0; segJ1[nseg] = p + e; nseg++;
        }
        if (t1 > boundary) {
            int s0 = max(t0, boundary);
            segStripe[nseg] = 31 - p;
            segJ0[nseg] = (31 - p) + (s0 - boundary);
            segJ1[nseg] = (31 - p) + (t1 - boundary);
            nseg++;
        }
    }

    const int lane   = tid & 31;
    const int warpid = tid >> 5;
    const int warpM  = warpid & 3;   // 4 warps over 128 M rows
    const int wN     = warpid >> 2;  // 2 warps over 128 N cols
    const int lrow = lane & 7, quad = lane >> 3;

    int aRow[2];
#pragma unroll
    for (int mi = 0; mi < 2; mi++) aRow[mi] = warpM * 32 + mi * 16 + lrow + (quad & 1) * 8;
    const int aCq = quad >> 1;
    int bRow[4];
#pragma unroll
    for (int pq = 0; pq < 4; pq++) bRow[pq] = wN * 64 + pq * 16 + lrow + (quad >> 1) * 8;
    const int bCq = quad & 1;

    const int erow = lane >> 2;        // accumulator row within fragment
    const int ecol = (lane & 3) * 2;   // accumulator col within n8

    for (int s = 0; s < nseg; s++) {
        const int stripe = segStripe[s];
        const int row0 = stripe * 128;
        const int j0 = segJ0[s], j1 = segJ1[s];

        // stage A stripe
#pragma unroll
        for (int it = 0; it < 16; it++) {
            int idx = tid + it * 256;
            int r = idx >> 5, c = idx & 31;
            cp16(sA + SWZ(r, c), Aptr + (row0 + r) * DIM + c * 8);
        }
        cp_commit();
        // stage first B tile
#pragma unroll
        for (int it = 0; it < 16; it++) {
            int idx = tid + it * 256;
            int r = idx >> 5, c = idx & 31;
            cp16(sB[0] + SWZ(r, c), Bptr + (j0 * 128 + r) * DIM + c * 8);
        }
        cp_commit();

        float part[4] = {0.f, 0.f, 0.f, 0.f};

        for (int j = j0; j < j1; j++) {
            const int buf = (j - j0) & 1;
            if (j + 1 < j1) {
                unsigned dB = sB[buf ^ 1];
#pragma unroll
                for (int it = 0; it < 16; it++) {
                    int idx = tid + it * 256;
                    int r = idx >> 5, c = idx & 31;
                    cp16(dB + SWZ(r, c), Bptr + ((j + 1) * 128 + r) * DIM + c * 8);
                }
                cp_commit();
                cp_wait<1>();
            } else {
                cp_wait<0>();
            }
            __syncthreads();

            unsigned sBj = sB[buf];
            float acc[2][8][4];
#pragma unroll
            for (int mi = 0; mi < 2; mi++)
#pragma unroll
                for (int ni = 0; ni < 8; ni++)
#pragma unroll
                    for (int k = 0; k < 4; k++) acc[mi][ni][k] = 0.f;

#pragma unroll
            for (int ks = 0; ks < 16; ks++) {
                unsigned a[2][4];
#pragma unroll
                for (int mi = 0; mi < 2; mi++) {
                    unsigned addr = sA + (aRow[mi] << 9) +
                                    (((2 * ks + aCq) ^ (aRow[mi] & 7)) << 4);
                    ldsm4(a[mi], addr);
                }
                unsigned b[4][4];
#pragma unroll
                for (int pq = 0; pq < 4; pq++) {
                    unsigned addr = sBj + (bRow[pq] << 9) +
                                    (((2 * ks + bCq) ^ (bRow[pq] & 7)) << 4);
                    ldsm4(b[pq], addr);
                }
#pragma unroll
                for (int mi = 0; mi < 2; mi++)
#pragma unroll
                    for (int ni = 0; ni < 8; ni++)
                        mma16816(acc[mi][ni], a[mi],
                                 b[ni >> 1][(ni & 1) * 2], b[ni >> 1][(ni & 1) * 2 + 1]);
            }

            // ---- epilogue: exp(10*sim), diag handling, row + col partials ----
            const bool isDiagTile = (j == stripe);
            const bool maskDiag = symmetric && isDiagTile;
            const bool recDiag  = (!symmetric) && isDiagTile;
            const bool doCol    = (!symmetric) || !isDiagTile;

            float colp0[8], colp1[8];
#pragma unroll
            for (int ni = 0; ni < 8; ni++) { colp0[ni] = 0.f; colp1[ni] = 0.f; }

#pragma unroll
            for (int mi = 0; mi < 2; mi++) {
                float s0 = 0.f, s1 = 0.f;
                int rr0 = warpM * 32 + mi * 16 + erow;
                int rr1 = rr0 + 8;
#pragma unroll
                for (int ni = 0; ni < 8; ni++) {
                    float c0 = acc[mi][ni][0], c1 = acc[mi][ni][1];
                    float c2 = acc[mi][ni][2], c3 = acc[mi][ni][3];
                    float e0 = fast_ex2(c0 * EXPSC), e1 = fast_ex2(c1 * EXPSC);
                    float e2 = fast_ex2(c2 * EXPSC), e3 = fast_ex2(c3 * EXPSC);
                    if (isDiagTile) {
                        int cc0 = wN * 64 + ni * 8 + ecol;
                        int cc1 = cc0 + 1;
                        if (maskDiag) {
                            if (rr0 == cc0) e0 = 0.f;
                            if (rr0 == cc1) e1 = 0.f;
                            if (rr1 == cc0) e2 = 0.f;
                            if (rr1 == cc1) e3 = 0.f;
                        } else if (recDiag) {
                            if (rr0 == cc0) g_diag[row0 + rr0] = c0 * INV_T;
                            if (rr0 == cc1) g_diag[row0 + rr0] = c1 * INV_T;
                            if (rr1 == cc0) g_diag[row0 + rr1] = c2 * INV_T;
                            if (rr1 == cc1) g_diag[row0 + rr1] = c3 * INV_T;
                        }
                    }
                    s0 += e0 + e1;
                    s1 += e2 + e3;
                    colp0[ni] += e0 + e2;
                    colp1[ni] += e1 + e3;
                }
                part[mi * 2 + 0] += s0;
                part[mi * 2 + 1] += s1;
            }

            // column partials: reduce over row-lanes within warp, stash in smem
            if (doCol) {
#pragma unroll
                for (int ni = 0; ni < 8; ni++) {
                    float v0 = colp0[ni], v1 = colp1[ni];
#pragma unroll
                    for (int o = 4; o <= 16; o <<= 1) {
                        v0 += __shfl_xor_sync(0xffffffffu, v0, o);
                        v1 += __shfl_xor_sync(0xffffffffu, v1, o);
                    }
                    if (lane < 4) {
                        int col = wN * 64 + ni * 8 + lane * 2;
                        colbuf[warpM * 128 + col]     = v0;
                        colbuf[warpM * 128 + col + 1] = v1;
                    }
                }
            }
            __syncthreads();
            if (doCol && tid < 128) {
                float v = colbuf[tid] + colbuf[128 + tid] +
                          colbuf[256 + tid] + colbuf[384 + tid];
                atomicAdd(&g_rowsum[colTarget][j * 128 + tid], v);
            }
        }

        // flush register row partials for this stripe
#pragma unroll
        for (int k = 0; k < 4; k++) {
            part[k] += __shfl_xor_sync(0xffffffffu, part[k], 1);
            part[k] += __shfl_xor_sync(0xffffffffu, part[k], 2);
        }
        if ((lane & 3) == 0) {
            int r = row0 + warpM * 32 + erow;
            atomicAdd(&g_rowsum[rowTarget][r],      part[0]);
            atomicAdd(&g_rowsum[rowTarget][r + 8],  part[1]);
            atomicAdd(&g_rowsum[rowTarget][r + 16], part[2]);
            atomicAdd(&g_rowsum[rowTarget][r + 24], part[3]);
        }
        __syncthreads();  // protect smem A before next segment's loads
    }
}

// ---------------------------------------------------------------------------
// Kernel 3: final losses.
// row i    : log(rowsum12[i] + rowsum11m[i]) - sim12[i,i]/T
// row N+i  : log(rowsum22m[i] + colsum12[i]) - sim12[i,i]/T
// ---------------------------------------------------------------------------
__global__ void loss_kernel(float* __restrict__ out) {
    int i = blockIdx.x * blockDim.x + threadIdx.x;
    if (i < NROWS) {
        float d = g_diag[i];
        out[i]         = logf(g_rowsum[0][i] + g_rowsum[2][i]) - d;
        out[NROWS + i] = logf(g_rowsum[3][i] + g_rowsum[1][i]) - d;
    }
}

extern "C" void kernel_launch(void* const* d_in, const int* in_sizes, int n_in,
                              void* d_out, int out_size) {
    const float* x1 = (const float*)d_in[0];
    const float* x2 = (const float*)d_in[1];

    normalize_kernel<<<1024, 256>>>(x1, x2);

    cudaFuncSetAttribute(simreduce_kernel,
                         cudaFuncAttributeMaxDynamicSharedMemorySize, SMEM_TOTAL);
    simreduce_kernel<<<128, 256, SMEM_TOTAL>>>();

    loss_kernel<<<16, 256>>>((float*)d_out);
}

// round 5
// speedup vs baseline: 1.4820x; 1.0259x over previous
#include <cuda_runtime.h>
#include <cuda_bf16.h>

#define NROWS 4096
#define DIM 256
#define INV_T 10.0f
#define EXPSC 14.4269504088896340736f  /* 10 * log2(e) */

// persistent device scratch (no allocations allowed)
__device__ __nv_bfloat16 g_z1[NROWS * DIM];
__device__ __nv_bfloat16 g_z2[NROWS * DIM];
// 0: rowsum(exp sim12), 1: colsum(exp sim12), 2: rowsum(exp sim11 masked), 3: rowsum(exp sim22 masked)
__device__ float g_rowsum[4][NROWS];
__device__ float g_diag[NROWS];        // sim12[i,i] * 10

__device__ __forceinline__ float fast_ex2(float x) {
    float y;
    asm("ex2.approx.f32 %0, %1;" : "=f"(y) : "f"(x));
    return y;
}

// ---------------------------------------------------------------------------
// Kernel 1: L2-normalize rows (eps clamp), fp32->bf16; zero g_rowsum.
// One warp per row.
// ---------------------------------------------------------------------------
__global__ void normalize_kernel(const float* __restrict__ x1,
                                 const float* __restrict__ x2) {
    int gt = blockIdx.x * blockDim.x + threadIdx.x;
    if (gt < 4 * NROWS) (&g_rowsum[0][0])[gt] = 0.0f;

    int gw = gt >> 5;
    int lane = threadIdx.x & 31;
    const float* src;
    __nv_bfloat16* dst;
    int row;
    if (gw < NROWS) { src = x1; dst = g_z1; row = gw; }
    else            { src = x2; dst = g_z2; row = gw - NROWS; }

    const float4* p = (const float4*)(src + row * DIM);
    float4 a = p[lane];
    float4 b = p[lane + 32];
    float s = a.x*a.x + a.y*a.y + a.z*a.z + a.w*a.w
            + b.x*b.x + b.y*b.y + b.z*b.z + b.w*b.w;
#pragma unroll
    for (int o = 16; o; o >>= 1) s += __shfl_xor_sync(0xffffffffu, s, o);
    float sc = 1.0f / fmaxf(sqrtf(s), 1e-8f);

    __nv_bfloat162 h0 = __floats2bfloat162_rn(a.x * sc, a.y * sc);
    __nv_bfloat162 h1 = __floats2bfloat162_rn(a.z * sc, a.w * sc);
    __nv_bfloat162 h2 = __floats2bfloat162_rn(b.x * sc, b.y * sc);
    __nv_bfloat162 h3 = __floats2bfloat162_rn(b.z * sc, b.w * sc);
    uint2 u0 = make_uint2(*(unsigned*)&h0, *(unsigned*)&h1);
    uint2 u1 = make_uint2(*(unsigned*)&h2, *(unsigned*)&h3);
    *(uint2*)(dst + row * DIM + lane * 4) = u0;
    *(uint2*)(dst + row * DIM + 128 + lane * 4) = u1;
}

// ---------------------------------------------------------------------------
// Kernel 2: fused tile-GEMM + exp row/col-reduce, symmetry-aware, 148 CTAs.
//   CTA 0..73   : sim12 (z1 x z2^T), 1024 tiles row-major, ~14 tiles each.
//                 rowsum -> g_rowsum[0], colsum -> g_rowsum[1], diag recorded.
//   CTA 74..110 : sim11 upper-tri (528 tiles, pair-ordered), 37 CTAs.
//   CTA 111..147: sim22 upper-tri, 37 CTAs.
//                 rowsum -> target; off-diag tiles also colsum -> target (symmetry).
// Per tile (128 rows x 128 cols x K=256): mma.sync bf16, ex2 epilogue,
// register row partials, shfl+REDG column partials.
// ---------------------------------------------------------------------------
#define SWZ(r, c) (((r) << 9) | ((((c) ^ ((r) & 7))) << 4))
#define SMEM_A 0
#define SMEM_B0 65536
#define SMEM_B1 131072
#define SMEM_TOTAL 196608

__device__ __forceinline__ void cp16(unsigned d, const void* s) {
    asm volatile("cp.async.cg.shared.global [%0], [%1], 16;" :: "r"(d), "l"(s));
}
__device__ __forceinline__ void cp_commit() {
    asm volatile("cp.async.commit_group;");
}
template <int n>
__device__ __forceinline__ void cp_wait() {
    asm volatile("cp.async.wait_group %0;" :: "n"(n));
}
__device__ __forceinline__ void ldsm4(unsigned (&r)[4], unsigned addr) {
    asm volatile("ldmatrix.sync.aligned.m8n8.x4.shared.b16 {%0,%1,%2,%3}, [%4];"
                 : "=r"(r[0]), "=r"(r[1]), "=r"(r[2]), "=r"(r[3]) : "r"(addr));
}
__device__ __forceinline__ void mma16816(float (&d)[4], const unsigned (&a)[4],
                                         unsigned b0, unsigned b1) {
    asm volatile(
        "mma.sync.aligned.m16n8k16.row.col.f32.bf16.bf16.f32 "
        "{%0,%1,%2,%3}, {%4,%5,%6,%7}, {%8,%9}, {%0,%1,%2,%3};"
        : "+f"(d[0]), "+f"(d[1]), "+f"(d[2]), "+f"(d[3])
        : "r"(a[0]), "r"(a[1]), "r"(a[2]), "r"(a[3]), "r"(b0), "r"(b1));
}

__device__ __forceinline__ void load_B(unsigned sb, const __nv_bfloat16* Bp,
                                       int j, int tid) {
#pragma unroll
    for (int it = 0; it < 16; it++) {
        int idx = tid + it * 256;
        int r = idx >> 5, c = idx & 31;
        cp16(sb + SWZ(r, c), Bp + (j * 128 + r) * DIM + c * 8);
    }
    cp_commit();
}

__global__ void __launch_bounds__(256, 1) simreduce_kernel() {
    extern __shared__ __align__(128) char smem[];
    unsigned sA = (unsigned)__cvta_generic_to_shared(smem + SMEM_A);
    unsigned sB[2] = {(unsigned)__cvta_generic_to_shared(smem + SMEM_B0),
                      (unsigned)__cvta_generic_to_shared(smem + SMEM_B1)};

    const int tid = threadIdx.x;
    const int bid = blockIdx.x;

    // ---- work decode: matrix + global tile range [g0, g1) ----
    int matrix, g0, g1;
    if (bid < 74) {
        matrix = 0;
        g0 = (1024 * bid) / 74;
        g1 = (1024 * (bid + 1)) / 74;
    } else if (bid < 111) {
        int c = bid - 74;
        matrix = 1;
        g0 = (528 * c) / 37;
        g1 = (528 * (c + 1)) / 37;
    } else {
        int c = bid - 111;
        matrix = 2;
        g0 = (528 * c) / 37;
        g1 = (528 * (c + 1)) / 37;
    }

    const __nv_bfloat16* Aptr = (matrix == 2) ? g_z2 : g_z1;
    const __nv_bfloat16* Bptr = (matrix == 1) ? g_z1 : g_z2;
    const int rowTarget = (matrix == 0) ? 0 : (1 + matrix);   // 0,2,3
    const int colTarget = (matrix == 0) ? 1 : (1 + matrix);   // 1,2,3
    const bool symmetric = (matrix != 0);

    const int lane   = tid & 31;
    const int warpid = tid >> 5;
    const int warpM  = warpid & 3;   // 4 warps over 128 M rows
    const int wN     = warpid >> 2;  // 2 warps over 128 N cols
    const int lrow = lane & 7, quad = lane >> 3;

    int aRow[2];
#pragma unroll
    for (int mi = 0; mi < 2; mi++) aRow[mi] = warpM * 32 + mi * 16 + lrow + (quad & 1) * 8;
    const int aCq = quad >> 1;
    int bRow[4];
#pragma unroll
    for (int pq = 0; pq < 4; pq++) bRow[pq] = wN * 64 + pq * 16 + lrow + (quad >> 1) * 8;
    const int bCq = quad & 1;

    const int erow = lane >> 2;        // accumulator row within fragment
    const int ecol = (lane & 3) * 2;   // accumulator col within n8

    int g = g0;
    while (g < g1) {
        // ---- segment decode: (stripe, j0, len) with stripe-contiguous tiles ----
        int stripe, j0, len;
        if (matrix == 0) {
            stripe = g >> 5;
            j0 = g & 31;
            len = min(g1 - g, 32 - j0);
        } else {
            int P = g / 33, o = g % 33;
            int run1 = 32 - P;           // stripe P: tiles j = P..31
            if (o < run1) {
                stripe = P; j0 = P + o;
                len = min(g1 - g, run1 - o);
            } else {                      // stripe 31-P: tiles j = 31-P..31
                stripe = 31 - P;
                int oo = o - run1;
                j0 = (31 - P) + oo;
                len = min(g1 - g, 33 - o);
            }
        }
        const int row0 = stripe * 128;

        __syncthreads();   // everyone done reading previous segment's smem

        // stage A stripe + first B tile
#pragma unroll
        for (int it = 0; it < 16; it++) {
            int idx = tid + it * 256;
            int r = idx >> 5, c = idx & 31;
            cp16(sA + SWZ(r, c), Aptr + (row0 + r) * DIM + c * 8);
        }
        cp_commit();
        load_B(sB[0], Bptr, j0, tid);

        float part[4] = {0.f, 0.f, 0.f, 0.f};

        for (int jj = 0; jj < len; jj++) {
            const int j = j0 + jj;
            const int buf = jj & 1;

            cp_wait<0>();
            __syncthreads();   // B[j] visible to all; buf^1 free to overwrite
            if (jj + 1 < len) load_B(sB[buf ^ 1], Bptr, j + 1, tid);

            unsigned sBj = sB[buf];
            float acc[2][8][4];
#pragma unroll
            for (int mi = 0; mi < 2; mi++)
#pragma unroll
                for (int ni = 0; ni < 8; ni++)
#pragma unroll
                    for (int k = 0; k < 4; k++) acc[mi][ni][k] = 0.f;

#pragma unroll
            for (int ks = 0; ks < 16; ks++) {
                unsigned a[2][4];
#pragma unroll
                for (int mi = 0; mi < 2; mi++) {
                    unsigned addr = sA + (aRow[mi] << 9) +
                                    (((2 * ks + aCq) ^ (aRow[mi] & 7)) << 4);
                    ldsm4(a[mi], addr);
                }
                unsigned b[4][4];
#pragma unroll
                for (int pq = 0; pq < 4; pq++) {
                    unsigned addr = sBj + (bRow[pq] << 9) +
                                    (((2 * ks + bCq) ^ (bRow[pq] & 7)) << 4);
                    ldsm4(b[pq], addr);
                }
#pragma unroll
                for (int mi = 0; mi < 2; mi++)
#pragma unroll
                    for (int ni = 0; ni < 8; ni++)
                        mma16816(acc[mi][ni], a[mi],
                                 b[ni >> 1][(ni & 1) * 2], b[ni >> 1][(ni & 1) * 2 + 1]);
            }

            // ---- epilogue: exp(10*sim), diag handling, row + col partials ----
            const bool isDiagTile = (j == stripe);
            const bool maskDiag = symmetric && isDiagTile;
            const bool recDiag  = (!symmetric) && isDiagTile;
            const bool doCol    = (!symmetric) || !isDiagTile;

            float colp0[8], colp1[8];
#pragma unroll
            for (int ni = 0; ni < 8; ni++) { colp0[ni] = 0.f; colp1[ni] = 0.f; }

#pragma unroll
            for (int mi = 0; mi < 2; mi++) {
                float s0 = 0.f, s1 = 0.f;
                int rr0 = warpM * 32 + mi * 16 + erow;
                int rr1 = rr0 + 8;
#pragma unroll
                for (int ni = 0; ni < 8; ni++) {
                    float c0 = acc[mi][ni][0], c1 = acc[mi][ni][1];
                    float c2 = acc[mi][ni][2], c3 = acc[mi][ni][3];
                    float e0 = fast_ex2(c0 * EXPSC), e1 = fast_ex2(c1 * EXPSC);
                    float e2 = fast_ex2(c2 * EXPSC), e3 = fast_ex2(c3 * EXPSC);
                    if (isDiagTile) {
                        int cc0 = wN * 64 + ni * 8 + ecol;
                        int cc1 = cc0 + 1;
                        if (maskDiag) {
                            if (rr0 == cc0) e0 = 0.f;
                            if (rr0 == cc1) e1 = 0.f;
                            if (rr1 == cc0) e2 = 0.f;
                            if (rr1 == cc1) e3 = 0.f;
                        } else if (recDiag) {
                            if (rr0 == cc0) g_diag[row0 + rr0] = c0 * INV_T;
                            if (rr0 == cc1) g_diag[row0 + rr0] = c1 * INV_T;
                            if (rr1 == cc0) g_diag[row0 + rr1] = c2 * INV_T;
                            if (rr1 == cc1) g_diag[row0 + rr1] = c3 * INV_T;
                        }
                    }
                    s0 += e0 + e1;
                    s1 += e2 + e3;
                    colp0[ni] += e0 + e2;
                    colp1[ni] += e1 + e3;
                }
                part[mi * 2 + 0] += s0;
                part[mi * 2 + 1] += s1;
            }

            // column partials: xor-shfl over the 8 row-lane groups, then REDG
            if (doCol) {
                float* ctgt = &g_rowsum[colTarget][j * 128];
#pragma unroll
                for (int ni = 0; ni < 8; ni++) {
                    float v0 = colp0[ni], v1 = colp1[ni];
#pragma unroll
                    for (int o = 4; o <= 16; o <<= 1) {
                        v0 += __shfl_xor_sync(0xffffffffu, v0, o);
                        v1 += __shfl_xor_sync(0xffffffffu, v1, o);
                    }
                    if (lane < 4) {
                        int col = wN * 64 + ni * 8 + lane * 2;
                        atomicAdd(ctgt + col,     v0);
                        atomicAdd(ctgt + col + 1, v1);
                    }
                }
            }
        }

        // flush register row partials for this segment's stripe
#pragma unroll
        for (int k = 0; k < 4; k++) {
            part[k] += __shfl_xor_sync(0xffffffffu, part[k], 1);
            part[k] += __shfl_xor_sync(0xffffffffu, part[k], 2);
        }
        if ((lane & 3) == 0) {
            int r = row0 + warpM * 32 + erow;
            atomicAdd(&g_rowsum[rowTarget][r],      part[0]);
            atomicAdd(&g_rowsum[rowTarget][r + 8],  part[1]);
            atomicAdd(&g_rowsum[rowTarget][r + 16], part[2]);
            atomicAdd(&g_rowsum[rowTarget][r + 24], part[3]);
        }

        g += len;
    }
}

// ---------------------------------------------------------------------------
// Kernel 3: final losses.
// row i    : log(rowsum12[i] + rowsum11m[i]) - sim12[i,i]/T
// row N+i  : log(rowsum22m[i] + colsum12[i]) - sim12[i,i]/T
// ---------------------------------------------------------------------------
__global__ void loss_kernel(float* __restrict__ out) {
    int i = blockIdx.x * blockDim.x + threadIdx.x;
    if (i < NROWS) {
        float d = g_diag[i];
        out[i]         = logf(g_rowsum[0][i] + g_rowsum[2][i]) - d;
        out[NROWS + i] = logf(g_rowsum[3][i] + g_rowsum[1][i]) - d;
    }
}

extern "C" void kernel_launch(void* const* d_in, const int* in_sizes, int n_in,
                              void* d_out, int out_size) {
    const float* x1 = (const float*)d_in[0];
    const float* x2 = (const float*)d_in[1];

    normalize_kernel<<<1024, 256>>>(x1, x2);

    cudaFuncSetAttribute(simreduce_kernel,
                         cudaFuncAttributeMaxDynamicSharedMemorySize, SMEM_TOTAL);
    simreduce_kernel<<<148, 256, SMEM_TOTAL>>>();

    loss_kernel<<<16, 256>>>((float*)d_out);
}

// round 7
// speedup vs baseline: 1.5665x; 1.0570x over previous
#include <cuda_runtime.h>
#include <cuda_bf16.h>

#define NROWS 4096
#define DIM 256
#define INV_T 10.0f
#define EXPSC 14.4269504088896340736f  /* 10 * log2(e) */

// persistent device scratch (no allocations allowed)
__device__ __nv_bfloat16 g_z1[NROWS * DIM];
__device__ __nv_bfloat16 g_z2[NROWS * DIM];
// 0: rowsum(exp sim12), 1: colsum(exp sim12), 2: rowsum(exp sim11 masked), 3: rowsum(exp sim22 masked)
__device__ float g_rowsum[4][NROWS];
__device__ float g_diag[NROWS];        // sim12[i,i] * 10

__device__ __forceinline__ float fast_ex2(float x) {
    float y;
    asm("ex2.approx.f32 %0, %1;" : "=f"(y) : "f"(x));
    return y;
}

// ---------------------------------------------------------------------------
// Kernel 1: L2-normalize rows (eps clamp), fp32->bf16; zero g_rowsum.
// One warp per row.
// ---------------------------------------------------------------------------
__global__ void normalize_kernel(const float* __restrict__ x1,
                                 const float* __restrict__ x2) {
    int gt = blockIdx.x * blockDim.x + threadIdx.x;
    if (gt < 4 * NROWS) (&g_rowsum[0][0])[gt] = 0.0f;

    int gw = gt >> 5;
    int lane = threadIdx.x & 31;
    const float* src;
    __nv_bfloat16* dst;
    int row;
    if (gw < NROWS) { src = x1; dst = g_z1; row = gw; }
    else            { src = x2; dst = g_z2; row = gw - NROWS; }

    const float4* p = (const float4*)(src + row * DIM);
    float4 a = p[lane];
    float4 b = p[lane + 32];
    float s = a.x*a.x + a.y*a.y + a.z*a.z + a.w*a.w
            + b.x*b.x + b.y*b.y + b.z*b.z + b.w*b.w;
#pragma unroll
    for (int o = 16; o; o >>= 1) s += __shfl_xor_sync(0xffffffffu, s, o);
    float sc = 1.0f / fmaxf(sqrtf(s), 1e-8f);

    __nv_bfloat162 h0 = __floats2bfloat162_rn(a.x * sc, a.y * sc);
    __nv_bfloat162 h1 = __floats2bfloat162_rn(a.z * sc, a.w * sc);
    __nv_bfloat162 h2 = __floats2bfloat162_rn(b.x * sc, b.y * sc);
    __nv_bfloat162 h3 = __floats2bfloat162_rn(b.z * sc, b.w * sc);
    uint2 u0 = make_uint2(*(unsigned*)&h0, *(unsigned*)&h1);
    uint2 u1 = make_uint2(*(unsigned*)&h2, *(unsigned*)&h3);
    *(uint2*)(dst + row * DIM + lane * 4) = u0;
    *(uint2*)(dst + row * DIM + 128 + lane * 4) = u1;
}

// ---------------------------------------------------------------------------
// Kernel 2: fused tile-GEMM + exp row/col-reduce. 148 CTAs, 2 warp-groups.
// Tile = 128 rows x 64 cols x K=256. Group 0 (warps 0-3) takes even local
// tiles, group 1 (warps 4-7) odd; each group has private double-buffered B
// and group-scoped named barriers, so one group's epilogue overlaps the
// other's HMMAs on every SMSP.
//   CTA 0..73   : sim12 (z1 x z2^T), 2048 tiles.  row->rs[0], col->rs[1], diag.
//   CTA 74..110 : sim11 upper-tri (1056 tiles, pair-ordered stripes).
//   CTA 111..147: sim22 upper-tri.   row->target; col->target by symmetry
//                 (diagonal-block tiles: rowsum only — full block computed).
// ---------------------------------------------------------------------------
#define SWZ(r, c) (((r) << 9) | ((((c) ^ ((r) & 7))) << 4))
#define SMEM_A 0
#define SMEM_B(grp, buf) (65536 + ((grp) * 2 + (buf)) * 32768)
#define SMEM_TOTAL 196608

__device__ __forceinline__ void cp16(unsigned d, const void* s) {
    asm volatile("cp.async.cg.shared.global [%0], [%1], 16;" :: "r"(d), "l"(s));
}
__device__ __forceinline__ void cp_commit() {
    asm volatile("cp.async.commit_group;");
}
template <int n>
__device__ __forceinline__ void cp_wait() {
    asm volatile("cp.async.wait_group %0;" :: "n"(n));
}
__device__ __forceinline__ void ldsm4(unsigned (&r)[4], unsigned addr) {
    asm volatile("ldmatrix.sync.aligned.m8n8.x4.shared.b16 {%0,%1,%2,%3}, [%4];"
                 : "=r"(r[0]), "=r"(r[1]), "=r"(r[2]), "=r"(r[3]) : "r"(addr));
}
__device__ __forceinline__ void mma16816(float (&d)[4], const unsigned (&a)[4],
                                         unsigned b0, unsigned b1) {
    asm volatile(
        "mma.sync.aligned.m16n8k16.row.col.f32.bf16.bf16.f32 "
        "{%0,%1,%2,%3}, {%4,%5,%6,%7}, {%8,%9}, {%0,%1,%2,%3};"
        : "+f"(d[0]), "+f"(d[1]), "+f"(d[2]), "+f"(d[3])
        : "r"(a[0]), "r"(a[1]), "r"(a[2]), "r"(a[3]), "r"(b0), "r"(b1));
}
__device__ __forceinline__ void bar_group(int g) {
    asm volatile("bar.sync %0, 128;" :: "r"(g + 1) : "memory");
}

// B tile: 64 rows x 256 K bf16 = 32KB. 128 threads x 16 cp16.
__device__ __forceinline__ void load_B(unsigned sb, const __nv_bfloat16* Bp,
                                       int j, int gtid) {
#pragma unroll
    for (int it = 0; it < 16; it++) {
        int idx = gtid + it * 128;
        int r = idx >> 5, c = idx & 31;
        cp16(sb + SWZ(r, c), Bp + (j * 64 + r) * DIM + c * 8);
    }
    cp_commit();
}

__global__ void __launch_bounds__(256, 1) simreduce_kernel() {
    extern __shared__ __align__(128) char smem[];
    const unsigned sbase = (unsigned)__cvta_generic_to_shared(smem);
    const unsigned sA = sbase + SMEM_A;

    const int tid = threadIdx.x;
    const int bid = blockIdx.x;
    const int wid = tid >> 5;
    const int lane = tid & 31;
    const int group = wid >> 2;      // 0: warps 0-3, 1: warps 4-7
    const int gtid = tid & 127;
    const int warpM = wid & 3;       // 32 M-rows per warp

    const unsigned sBg[2] = {sbase + SMEM_B(group, 0), sbase + SMEM_B(group, 1)};

    // ---- work decode: matrix + global tile range [g0, g1) over 64-col tiles ----
    int matrix, g0, g1;
    if (bid < 74) {
        matrix = 0;
        g0 = (2048 * bid) / 74;
        g1 = (2048 * (bid + 1)) / 74;
    } else if (bid < 111) {
        int c = bid - 74;
        matrix = 1;
        g0 = (1056 * c) / 37;
        g1 = (1056 * (c + 1)) / 37;
    } else {
        int c = bid - 111;
        matrix = 2;
        g0 = (1056 * c) / 37;
        g1 = (1056 * (c + 1)) / 37;
    }

    const __nv_bfloat16* Aptr = (matrix == 2) ? g_z2 : g_z1;
    const __nv_bfloat16* Bptr = (matrix == 1) ? g_z1 : g_z2;
    const int rowTarget = (matrix == 0) ? 0 : (1 + matrix);
    const int colTarget = (matrix == 0) ? 1 : (1 + matrix);
    const bool symmetric = (matrix != 0);

    const int lrow = lane & 7, quad = lane >> 3;
    int aRow[2];
#pragma unroll
    for (int mi = 0; mi < 2; mi++) aRow[mi] = warpM * 32 + mi * 16 + lrow + (quad & 1) * 8;
    const int aCq = quad >> 1;
    int bRow[4];
#pragma unroll
    for (int pq = 0; pq < 4; pq++) bRow[pq] = pq * 16 + lrow + (quad >> 1) * 8;
    const int bCq = quad & 1;

    const int erow = lane >> 2;        // accumulator row within fragment
    const int ecol = (lane & 3) * 2;   // accumulator col within n8

    int g = g0;
    while (g < g1) {
        // ---- segment decode: stripe + local tile range [j0, j0+len) (64-col j) ----
        int stripe, j0, len;
        if (matrix == 0) {
            stripe = g >> 6;
            j0 = g & 63;
            len = min(g1 - g, 64 - j0);
        } else {
            int P = g / 66, o = g % 66;
            int run1 = 64 - 2 * P;       // stripe P: tiles j = 2P..63
            if (o < run1) {
                stripe = P; j0 = 2 * P + o;
                len = min(g1 - g, run1 - o);
            } else {                      // stripe 31-P: tiles j = 2(31-P)..63
                stripe = 31 - P;
                int oo = o - run1;
                j0 = 2 * (31 - P) + oo;
                len = min(g1 - g, 66 - o);
            }
        }
        const int row0 = stripe * 128;

        __syncthreads();   // both groups done with previous segment's smem

        // ---- prologue: B_first(group), A (all), B_second(group) ----
        if (group < len) load_B(sBg[0], Bptr, j0 + group, gtid);
        else             cp_commit();                              // c1
#pragma unroll
        for (int it = 0; it < 16; it++) {
            int idx = tid + it * 256;
            int r = idx >> 5, c = idx & 31;
            cp16(sA + SWZ(r, c), Aptr + (row0 + r) * DIM + c * 8);
        }
        cp_commit();                                               // c2 (A)
        if (group + 2 < len) load_B(sBg[1], Bptr, j0 + group + 2, gtid);
        else                 cp_commit();                          // c3
        cp_wait<1>();        // c1 + c2 (own B_first + A portion) complete
        __syncthreads();     // everyone's A portion landed

        float part[4] = {0.f, 0.f, 0.f, 0.f};

        int t = 0;
        for (int jj = group; jj < len; jj += 2, t++) {
            const int j = j0 + jj;
            const unsigned sBj = sBg[t & 1];

            cp_wait<1>();        // current buffer's copies complete (this thread)
            bar_group(group);    // whole group's copies visible

            float acc[2][8][4];
#pragma unroll
            for (int mi = 0; mi < 2; mi++)
#pragma unroll
                for (int ni = 0; ni < 8; ni++)
#pragma unroll
                    for (int k = 0; k < 4; k++) acc[mi][ni][k] = 0.f;

#pragma unroll
            for (int ks = 0; ks < 16; ks++) {
                unsigned a[2][4];
#pragma unroll
                for (int mi = 0; mi < 2; mi++) {
                    unsigned addr = sA + (aRow[mi] << 9) +
                                    (((2 * ks + aCq) ^ (aRow[mi] & 7)) << 4);
                    ldsm4(a[mi], addr);
                }
                unsigned b[4][4];
#pragma unroll
                for (int pq = 0; pq < 4; pq++) {
                    unsigned addr = sBj + (bRow[pq] << 9) +
                                    (((2 * ks + bCq) ^ (bRow[pq] & 7)) << 4);
                    ldsm4(b[pq], addr);
                }
#pragma unroll
                for (int mi = 0; mi < 2; mi++)
#pragma unroll
                    for (int ni = 0; ni < 8; ni++)
                        mma16816(acc[mi][ni], a[mi],
                                 b[ni >> 1][(ni & 1) * 2], b[ni >> 1][(ni & 1) * 2 + 1]);
            }

            bar_group(group);    // group done reading sBj; safe to refill
            if (jj + 4 < len) load_B(sBg[t & 1], Bptr, j + 4, gtid);
            else              cp_commit();

            // ---- epilogue: exp(10*sim), diag handling, row + col partials ----
            const bool maybeDiag = ((j >> 1) == stripe);
            const bool maskDiag = symmetric && maybeDiag;
            const bool recDiag  = (!symmetric) && maybeDiag;
            // diagonal-block tiles of symmetric matrices: full block computed by
            // rowsums, so colsums would double-count -> skip them there.
            const bool doCol    = (!symmetric) || !maybeDiag;

            float colp0[8], colp1[8];
#pragma unroll
            for (int ni = 0; ni < 8; ni++) { colp0[ni] = 0.f; colp1[ni] = 0.f; }

#pragma unroll
            for (int mi = 0; mi < 2; mi++) {
                float s0 = 0.f, s1 = 0.f;
                int rr0 = row0 + warpM * 32 + mi * 16 + erow;   // global rows
                int rr1 = rr0 + 8;
#pragma unroll
                for (int ni = 0; ni < 8; ni++) {
                    float c0 = acc[mi][ni][0], c1 = acc[mi][ni][1];
                    float c2 = acc[mi][ni][2], c3 = acc[mi][ni][3];
                    float e0 = fast_ex2(c0 * EXPSC), e1 = fast_ex2(c1 * EXPSC);
                    float e2 = fast_ex2(c2 * EXPSC), e3 = fast_ex2(c3 * EXPSC);
                    if (maybeDiag) {
                        int cc0 = j * 64 + ni * 8 + ecol;        // global cols
                        int cc1 = cc0 + 1;
                        if (maskDiag) {
                            if (rr0 == cc0) e0 = 0.f;
                            if (rr0 == cc1) e1 = 0.f;
                            if (rr1 == cc0) e2 = 0.f;
                            if (rr1 == cc1) e3 = 0.f;
                        } else if (recDiag) {
                            if (rr0 == cc0) g_diag[rr0] = c0 * INV_T;
                            if (rr0 == cc1) g_diag[rr0] = c1 * INV_T;
                            if (rr1 == cc0) g_diag[rr1] = c2 * INV_T;
                            if (rr1 == cc1) g_diag[rr1] = c3 * INV_T;
                        }
                    }
                    s0 += e0 + e1;
                    s1 += e2 + e3;
                    colp0[ni] += e0 + e2;
                    colp1[ni] += e1 + e3;
                }
                part[mi * 2 + 0] += s0;
                part[mi * 2 + 1] += s1;
            }

            // column partials: xor-shfl over the 8 erow groups, then REDG
            if (doCol) {
                float* ctgt = &g_rowsum[colTarget][j * 64];
#pragma unroll
                for (int ni = 0; ni < 8; ni++) {
                    float v0 = colp0[ni], v1 = colp1[ni];
#pragma unroll
                    for (int o = 4; o <= 16; o <<= 1) {
                        v0 += __shfl_xor_sync(0xffffffffu, v0, o);
                        v1 += __shfl_xor_sync(0xffffffffu, v1, o);
                    }
                    if (lane < 4) {
                        int col = ni * 8 + lane * 2;
                        atomicAdd(ctgt + col,     v0);
                        atomicAdd(ctgt + col + 1, v1);
                    }
                }
            }
        }

        // flush register row partials for this segment's stripe
#pragma unroll
        for (int k = 0; k < 4; k++) {
            part[k] += __shfl_xor_sync(0xffffffffu, part[k], 1);
            part[k] += __shfl_xor_sync(0xffffffffu, part[k], 2);
        }
        if ((lane & 3) == 0) {
            int r = row0 + warpM * 32 + erow;
            atomicAdd(&g_rowsum[rowTarget][r],      part[0]);
            atomicAdd(&g_rowsum[rowTarget][r + 8],  part[1]);
            atomicAdd(&g_rowsum[rowTarget][r + 16], part[2]);
            atomicAdd(&g_rowsum[rowTarget][r + 24], part[3]);
        }

        g += len;
    }
}

// ---------------------------------------------------------------------------
// Kernel 3: final losses.
// row i    : log(rowsum12[i] + rowsum11m[i]) - sim12[i,i]/T
// row N+i  : log(rowsum22m[i] + colsum12[i]) - sim12[i,i]/T
// ---------------------------------------------------------------------------
__global__ void loss_kernel(float* __restrict__ out) {
    int i = blockIdx.x * blockDim.x + threadIdx.x;
    if (i < NROWS) {
        float d = g_diag[i];
        out[i]         = logf(g_rowsum[0][i] + g_rowsum[2][i]) - d;
        out[NROWS + i] = logf(g_rowsum[3][i] + g_rowsum[1][i]) - d;
    }
}

extern "C" void kernel_launch(void* const* d_in, const int* in_sizes, int n_in,
                              void* d_out, int out_size) {
    const float* x1 = (const float*)d_in[0];
    const float* x2 = (const float*)d_in[1];

    normalize_kernel<<<1024, 256>>>(x1, x2);

    cudaFuncSetAttribute(simreduce_kernel,
                         cudaFuncAttributeMaxDynamicSharedMemorySize, SMEM_TOTAL);
    simreduce_kernel<<<148, 256, SMEM_TOTAL>>>();

    loss_kernel<<<16, 256>>>((float*)d_out);
}

// round 8
// speedup vs baseline: 1.7787x; 1.1355x over previous
#include <cuda_runtime.h>
#include <cuda_fp16.h>

#define NROWS 4096
#define DIM 256
#define INV_T 10.0f
#define EXPSC 14.4269504088896340736f  /* 10 * log2(e) */

// persistent device scratch (no allocations allowed)
__device__ __half g_z1[NROWS * DIM];
__device__ __half g_z2[NROWS * DIM];
// 0: rowsum(exp sim12, diag zeroed), 1: colsum(exp sim12, diag zeroed),
// 2: rowsum(exp sim11 masked), 3: rowsum(exp sim22 masked)
__device__ float g_rowsum[4][NROWS];

__device__ __forceinline__ float fast_ex2(float x) {
    float y;
    asm("ex2.approx.f32 %0, %1;" : "=f"(y) : "f"(x));
    return y;
}

// ---------------------------------------------------------------------------
// Kernel 1: L2-normalize rows (eps clamp), fp32->fp16; zero g_rowsum.
// One warp per row.
// ---------------------------------------------------------------------------
__global__ void normalize_kernel(const float* __restrict__ x1,
                                 const float* __restrict__ x2) {
    int gt = blockIdx.x * blockDim.x + threadIdx.x;
    if (gt < 4 * NROWS) (&g_rowsum[0][0])[gt] = 0.0f;

    int gw = gt >> 5;
    int lane = threadIdx.x & 31;
    const float* src;
    __half* dst;
    int row;
    if (gw < NROWS) { src = x1; dst = g_z1; row = gw; }
    else            { src = x2; dst = g_z2; row = gw - NROWS; }

    const float4* p = (const float4*)(src + row * DIM);
    float4 a = p[lane];
    float4 b = p[lane + 32];
    float s = a.x*a.x + a.y*a.y + a.z*a.z + a.w*a.w
            + b.x*b.x + b.y*b.y + b.z*b.z + b.w*b.w;
#pragma unroll
    for (int o = 16; o; o >>= 1) s += __shfl_xor_sync(0xffffffffu, s, o);
    float sc = 1.0f / fmaxf(sqrtf(s), 1e-8f);

    __half2 h0 = __floats2half2_rn(a.x * sc, a.y * sc);
    __half2 h1 = __floats2half2_rn(a.z * sc, a.w * sc);
    __half2 h2 = __floats2half2_rn(b.x * sc, b.y * sc);
    __half2 h3 = __floats2half2_rn(b.z * sc, b.w * sc);
    uint2 u0 = make_uint2(*(unsigned*)&h0, *(unsigned*)&h1);
    uint2 u1 = make_uint2(*(unsigned*)&h2, *(unsigned*)&h3);
    *(uint2*)(dst + row * DIM + lane * 4) = u0;
    *(uint2*)(dst + row * DIM + 128 + lane * 4) = u1;
}

// ---------------------------------------------------------------------------
// Kernel 2: fused tile-GEMM + exp row/col-reduce. 148 CTAs, 2 warp-groups,
// fp16 inputs + fp16 accumulate (2x HMMA rate). Diagonal entries are ZEROED
// for all matrices (exact); loss kernel adds back exp(10*diag12) from an
// exact fp32 dot product.
// Tile = 128 rows x 64 cols x K=256. Group g takes local tiles jj % 2 == g,
// private double-buffered B, group-scoped named barriers.
//   CTA 0..73   : sim12 (z1 x z2^T), 2048 tiles.  row->rs[0], col->rs[1].
//   CTA 74..110 : sim11 upper-tri (1056 tiles, pair-ordered stripes).
//   CTA 111..147: sim22 upper-tri.   row->target; col->target by symmetry
//                 (diagonal-block tiles: rowsum only — full block computed).
// ---------------------------------------------------------------------------
#define SWZ(r, c) (((r) << 9) | ((((c) ^ ((r) & 7))) << 4))
#define SMEM_A 0
#define SMEM_B(grp, buf) (65536 + ((grp) * 2 + (buf)) * 32768)
#define SMEM_TOTAL 196608

__device__ __forceinline__ void cp16(unsigned d, const void* s) {
    asm volatile("cp.async.cg.shared.global [%0], [%1], 16;" :: "r"(d), "l"(s));
}
__device__ __forceinline__ void cp_commit() {
    asm volatile("cp.async.commit_group;");
}
template <int n>
__device__ __forceinline__ void cp_wait() {
    asm volatile("cp.async.wait_group %0;" :: "n"(n));
}
__device__ __forceinline__ void ldsm4(unsigned (&r)[4], unsigned addr) {
    asm volatile("ldmatrix.sync.aligned.m8n8.x4.shared.b16 {%0,%1,%2,%3}, [%4];"
                 : "=r"(r[0]), "=r"(r[1]), "=r"(r[2]), "=r"(r[3]) : "r"(addr));
}
__device__ __forceinline__ void mma16816h(unsigned (&d)[2], const unsigned (&a)[4],
                                          unsigned b0, unsigned b1) {
    asm volatile(
        "mma.sync.aligned.m16n8k16.row.col.f16.f16.f16.f16 "
        "{%0,%1}, {%2,%3,%4,%5}, {%6,%7}, {%0,%1};"
        : "+r"(d[0]), "+r"(d[1])
        : "r"(a[0]), "r"(a[1]), "r"(a[2]), "r"(a[3]), "r"(b0), "r"(b1));
}
__device__ __forceinline__ void bar_group(int g) {
    asm volatile("bar.sync %0, 128;" :: "r"(g + 1) : "memory");
}

// B tile: 64 rows x 256 K fp16 = 32KB. 128 threads x 16 cp16.
__device__ __forceinline__ void load_B(unsigned sb, const __half* Bp,
                                       int j, int gtid) {
#pragma unroll
    for (int it = 0; it < 16; it++) {
        int idx = gtid + it * 128;
        int r = idx >> 5, c = idx & 31;
        cp16(sb + SWZ(r, c), Bp + (j * 64 + r) * DIM + c * 8);
    }
    cp_commit();
}

__global__ void __launch_bounds__(256, 1) simreduce_kernel() {
    extern __shared__ __align__(128) char smem[];
    const unsigned sbase = (unsigned)__cvta_generic_to_shared(smem);
    const unsigned sA = sbase + SMEM_A;

    const int tid = threadIdx.x;
    const int bid = blockIdx.x;
    const int wid = tid >> 5;
    const int lane = tid & 31;
    const int group = wid >> 2;      // 0: warps 0-3, 1: warps 4-7
    const int gtid = tid & 127;
    const int warpM = wid & 3;       // 32 M-rows per warp

    const unsigned sBg[2] = {sbase + SMEM_B(group, 0), sbase + SMEM_B(group, 1)};

    // ---- work decode: matrix + global tile range [g0, g1) over 64-col tiles ----
    int matrix, g0, g1;
    if (bid < 74) {
        matrix = 0;
        g0 = (2048 * bid) / 74;
        g1 = (2048 * (bid + 1)) / 74;
    } else if (bid < 111) {
        int c = bid - 74;
        matrix = 1;
        g0 = (1056 * c) / 37;
        g1 = (1056 * (c + 1)) / 37;
    } else {
        int c = bid - 111;
        matrix = 2;
        g0 = (1056 * c) / 37;
        g1 = (1056 * (c + 1)) / 37;
    }

    const __half* Aptr = (matrix == 2) ? g_z2 : g_z1;
    const __half* Bptr = (matrix == 1) ? g_z1 : g_z2;
    const int rowTarget = (matrix == 0) ? 0 : (1 + matrix);
    const int colTarget = (matrix == 0) ? 1 : (1 + matrix);
    const bool symmetric = (matrix != 0);

    const int lrow = lane & 7, quad = lane >> 3;
    int aRow[2];
#pragma unroll
    for (int mi = 0; mi < 2; mi++) aRow[mi] = warpM * 32 + mi * 16 + lrow + (quad & 1) * 8;
    const int aCq = quad >> 1;
    int bRow[4];
#pragma unroll
    for (int pq = 0; pq < 4; pq++) bRow[pq] = pq * 16 + lrow + (quad >> 1) * 8;
    const int bCq = quad & 1;

    const int erow = lane >> 2;        // accumulator row within fragment
    const int ecol = (lane & 3) * 2;   // accumulator col within n8

    int g = g0;
    while (g < g1) {
        // ---- segment decode: stripe + local tile range [j0, j0+len) (64-col j) ----
        int stripe, j0, len;
        if (matrix == 0) {
            stripe = g >> 6;
            j0 = g & 63;
            len = min(g1 - g, 64 - j0);
        } else {
            int P = g / 66, o = g % 66;
            int run1 = 64 - 2 * P;       // stripe P: tiles j = 2P..63
            if (o < run1) {
                stripe = P; j0 = 2 * P + o;
                len = min(g1 - g, run1 - o);
            } else {                      // stripe 31-P: tiles j = 2(31-P)..63
                stripe = 31 - P;
                int oo = o - run1;
                j0 = 2 * (31 - P) + oo;
                len = min(g1 - g, 66 - o);
            }
        }
        const int row0 = stripe * 128;

        __syncthreads();   // both groups done with previous segment's smem

        // ---- prologue: B_first(group), A (all), B_second(group) ----
        if (group < len) load_B(sBg[0], Bptr, j0 + group, gtid);
        else             cp_commit();                              // c1
#pragma unroll
        for (int it = 0; it < 16; it++) {
            int idx = tid + it * 256;
            int r = idx >> 5, c = idx & 31;
            cp16(sA + SWZ(r, c), Aptr + (row0 + r) * DIM + c * 8);
        }
        cp_commit();                                               // c2 (A)
        if (group + 2 < len) load_B(sBg[1], Bptr, j0 + group + 2, gtid);
        else                 cp_commit();                          // c3
        cp_wait<1>();        // c1 + c2 (own B_first + A portion) complete
        __syncthreads();     // everyone's A portion landed

        float part[4] = {0.f, 0.f, 0.f, 0.f};

        int t = 0;
        for (int jj = group; jj < len; jj += 2, t++) {
            const int j = j0 + jj;
            const unsigned sBj = sBg[t & 1];

            cp_wait<1>();        // current buffer's copies complete (this thread)
            bar_group(group);    // whole group's copies visible

            unsigned acc[2][8][2];
#pragma unroll
            for (int mi = 0; mi < 2; mi++)
#pragma unroll
                for (int ni = 0; ni < 8; ni++) {
                    acc[mi][ni][0] = 0u;
                    acc[mi][ni][1] = 0u;
                }

#pragma unroll
            for (int ks = 0; ks < 16; ks++) {
                unsigned a[2][4];
#pragma unroll
                for (int mi = 0; mi < 2; mi++) {
                    unsigned addr = sA + (aRow[mi] << 9) +
                                    (((2 * ks + aCq) ^ (aRow[mi] & 7)) << 4);
                    ldsm4(a[mi], addr);
                }
                unsigned b[4][4];
#pragma unroll
                for (int pq = 0; pq < 4; pq++) {
                    unsigned addr = sBj + (bRow[pq] << 9) +
                                    (((2 * ks + bCq) ^ (bRow[pq] & 7)) << 4);
                    ldsm4(b[pq], addr);
                }
#pragma unroll
                for (int mi = 0; mi < 2; mi++)
#pragma unroll
                    for (int ni = 0; ni < 8; ni++)
                        mma16816h(acc[mi][ni], a[mi],
                                  b[ni >> 1][(ni & 1) * 2], b[ni >> 1][(ni & 1) * 2 + 1]);
            }

            bar_group(group);    // group done reading sBj; safe to refill
            if (jj + 4 < len) load_B(sBg[t & 1], Bptr, j + 4, gtid);
            else              cp_commit();

            // ---- epilogue: exp(10*sim), diag zeroing, row + col partials ----
            const bool maybeDiag = ((j >> 1) == stripe);   // tile touches diagonal
            // diagonal-block tiles of symmetric matrices: full block computed by
            // rowsums, so colsums would double-count -> skip them there.
            const bool doCol = (!symmetric) || !maybeDiag;

            float colp0[8], colp1[8];
#pragma unroll
            for (int ni = 0; ni < 8; ni++) { colp0[ni] = 0.f; colp1[ni] = 0.f; }

#pragma unroll
            for (int mi = 0; mi < 2; mi++) {
                float s0 = 0.f, s1 = 0.f;
                int rr0 = row0 + warpM * 32 + mi * 16 + erow;   // global rows
                int rr1 = rr0 + 8;
#pragma unroll
                for (int ni = 0; ni < 8; ni++) {
                    float2 f01 = __half22float2(*(__half2*)&acc[mi][ni][0]);
                    float2 f23 = __half22float2(*(__half2*)&acc[mi][ni][1]);
                    float e0 = fast_ex2(f01.x * EXPSC), e1 = fast_ex2(f01.y * EXPSC);
                    float e2 = fast_ex2(f23.x * EXPSC), e3 = fast_ex2(f23.y * EXPSC);
                    if (maybeDiag) {
                        int cc0 = j * 64 + ni * 8 + ecol;        // global cols
                        int cc1 = cc0 + 1;
                        if (rr0 == cc0) e0 = 0.f;   // zero diagonal (exact);
                        if (rr0 == cc1) e1 = 0.f;   // sim12 diag re-added in loss
                        if (rr1 == cc0) e2 = 0.f;
                        if (rr1 == cc1) e3 = 0.f;
                    }
                    s0 += e0 + e1;
                    s1 += e2 + e3;
                    colp0[ni] += e0 + e2;
                    colp1[ni] += e1 + e3;
                }
                part[mi * 2 + 0] += s0;
                part[mi * 2 + 1] += s1;
            }

            // column partials: xor-shfl over the 8 erow groups, then REDG
            if (doCol) {
                float* ctgt = &g_rowsum[colTarget][j * 64];
#pragma unroll
                for (int ni = 0; ni < 8; ni++) {
                    float v0 = colp0[ni], v1 = colp1[ni];
#pragma unroll
                    for (int o = 4; o <= 16; o <<= 1) {
                        v0 += __shfl_xor_sync(0xffffffffu, v0, o);
                        v1 += __shfl_xor_sync(0xffffffffu, v1, o);
                    }
                    if (lane < 4) {
                        int col = ni * 8 + lane * 2;
                        atomicAdd(ctgt + col,     v0);
                        atomicAdd(ctgt + col + 1, v1);
                    }
                }
            }
        }

        // flush register row partials for this segment's stripe
#pragma unroll
        for (int k = 0; k < 4; k++) {
            part[k] += __shfl_xor_sync(0xffffffffu, part[k], 1);
            part[k] += __shfl_xor_sync(0xffffffffu, part[k], 2);
        }
        if ((lane & 3) == 0) {
            int r = row0 + warpM * 32 + erow;
            atomicAdd(&g_rowsum[rowTarget][r],      part[0]);
            atomicAdd(&g_rowsum[rowTarget][r + 8],  part[1]);
            atomicAdd(&g_rowsum[rowTarget][r + 16], part[2]);
            atomicAdd(&g_rowsum[rowTarget][r + 24], part[3]);
        }

        g += len;
    }
}

// ---------------------------------------------------------------------------
// Kernel 3: final losses. One warp per row: exact fp32 diag dot, then
// row i    : log(rowsum12[i] + rowsum11m[i] + e^{10 d}) - 10 d
// row N+i  : log(rowsum22m[i] + colsum12[i] + e^{10 d}) - 10 d
// ---------------------------------------------------------------------------
__global__ void loss_kernel(float* __restrict__ out) {
    int w = (blockIdx.x * blockDim.x + threadIdx.x) >> 5;
    int lane = threadIdx.x & 31;
    if (w >= NROWS) return;

    const __half2* p1 = (const __half2*)(g_z1 + w * DIM);
    const __half2* p2 = (const __half2*)(g_z2 + w * DIM);
    float d = 0.f;
#pragma unroll
    for (int i = 0; i < 4; i++) {
        float2 a = __half22float2(p1[lane * 4 + i]);
        float2 b = __half22float2(p2[lane * 4 + i]);
        d += a.x * b.x + a.y * b.y;
    }
#pragma unroll
    for (int o = 16; o; o >>= 1) d += __shfl_xor_sync(0xffffffffu, d, o);

    if (lane == 0) {
        float ed = fast_ex2(d * EXPSC);
        float dl = d * INV_T;
        out[w]         = logf(g_rowsum[0][w] + g_rowsum[2][w] + ed) - dl;
        out[NROWS + w] = logf(g_rowsum[3][w] + g_rowsum[1][w] + ed) - dl;
    }
}

extern "C" void kernel_launch(void* const* d_in, const int* in_sizes, int n_in,
                              void* d_out, int out_size) {
    const float* x1 = (const float*)d_in[0];
    const float* x2 = (const float*)d_in[1];

    normalize_kernel<<<1024, 256>>>(x1, x2);

    cudaFuncSetAttribute(simreduce_kernel,
                         cudaFuncAttributeMaxDynamicSharedMemorySize, SMEM_TOTAL);
    simreduce_kernel<<<148, 256, SMEM_TOTAL>>>();

    loss_kernel<<<512, 256>>>((float*)d_out);
}